// round 7
// baseline (speedup 1.0000x reference)
#include <cuda_runtime.h>
#include <math.h>

// ---------------- problem constants ----------------
#define NB   64        // batch
#define NN_  200       // nodes
#define NU   64        // rnn units
#define NL   4         // layers
#define NT   12        // input_len == output_len
#define F0   264       // layer-0 features (200 + 64)
#define F1   128       // layer>0 features (64 + 64)
#define BF0  (F0*NB)   // 16896
#define BF1  (F1*NB)   // 8192
#define SEG0 (NN_*BF0) // 3,379,200
#define NNSQ 40000     // N*N
#define HSZ  (NN_*NU*NB)   // 819200, hidden layout [n][u][b]

typedef unsigned long long ull;

// ---------------- scratch (device globals; no allocation allowed) ----------
__device__ float g_X[3*SEG0];          // [X0 ; X1 ; X2], row=node, col=f*64+b
__device__ float g_SS[400*200];        // [S ; 2S^2 - I]
__device__ float g_h[NL][HSZ];         // hidden per layer, [n][u][b]
__device__ float g_u[HSZ];             // update gate, [n][u][b]
__device__ float g_W[746496];          // reordered weights [k][f][o]

// ---------------- f32x2 helpers ----------------
__device__ __forceinline__ ull pack2(float lo, float hi) {
    ull r; asm("mov.b64 %0,{%1,%2};" : "=l"(r) : "f"(lo), "f"(hi)); return r;
}
__device__ __forceinline__ ull ffma2(ull a, ull b, ull c) {
    ull d; asm("fma.rn.f32x2 %0,%1,%2,%3;" : "=l"(d) : "l"(a), "l"(b), "l"(c)); return d;
}
__device__ __forceinline__ float2 upk(ull v) {
    float2 f; asm("mov.b64 {%0,%1},%2;" : "=f"(f.x), "=f"(f.y) : "l"(v)); return f;
}

// ---------------- setup kernels ----------------
__global__ void build_SS(const float* __restrict__ S) {
    int m = blockIdx.x;
    int k = threadIdx.x;
    if (k >= 200) return;
    if (m < 200) { g_SS[m*200 + k] = S[m*200 + k]; return; }
    int r = m - 200;
    float acc = 0.f;
    for (int j = 0; j < 200; j++) acc += S[r*200 + j] * S[j*200 + k];
    g_SS[m*200 + k] = 2.f*acc - (r == k ? 1.f : 0.f);
}

// src rows are (f*3+k); dst is [k][f][o] contiguous
__global__ void reorder_W(const float* __restrict__ src, int dstOff, int F, int O) {
    int idx = blockIdx.x * blockDim.x + threadIdx.x;
    int tot = 3 * F * O;
    if (idx >= tot) return;
    int k   = idx / (F * O);
    int rem = idx - k * F * O;
    int f   = rem / O;
    int o   = rem - f * O;
    g_W[dstOff + idx] = src[(f*3 + k)*O + o];
}

__global__ void zero_h() {
    int idx = blockIdx.x * blockDim.x + threadIdx.x;
    if (idx < NL*HSZ) ((float*)g_h)[idx] = 0.f;
}

// ---------------- pack kernels ----------------
// layer-0 input features from src[b*strideB + n*200 + f] -> g_X[n][f][b]
__global__ void pack_l0_input(const float* __restrict__ src, int strideB) {
    __shared__ float s[32][33];
    int n  = blockIdx.x;
    int f0 = blockIdx.y * 32;
    int b0 = blockIdx.z * 32;
    int tx = threadIdx.x, ty = threadIdx.y;     // 32 x 8
    if (src) {
        #pragma unroll
        for (int i = 0; i < 4; i++) {
            int b = b0 + ty + 8*i;
            int f = f0 + tx;
            s[ty + 8*i][tx] = (f < 200) ? src[b*strideB + n*200 + f] : 0.f;
        }
    } else {
        #pragma unroll
        for (int i = 0; i < 4; i++) s[ty + 8*i][tx] = 0.f;
    }
    __syncthreads();
    #pragma unroll
    for (int i = 0; i < 4; i++) {
        int f = f0 + ty + 8*i;
        if (f < 200) g_X[n*BF0 + f*64 + b0 + tx] = s[tx][ty + 8*i];
    }
}

// copy h[srcLayer] into X0 at feature offset dstF
__global__ void pack_h_block(int srcLayer, int dstF, int BFl) {
    int idx = blockIdx.x * blockDim.x + threadIdx.x;
    if (idx >= HSZ) return;
    int n   = idx >> 12;
    int rem = idx & 4095;
    g_X[n*BFl + dstF*64 + rem] = g_h[srcLayer][idx];
}

// l>0: h[l-1] -> X0 input half, h[l] -> X0 state half (BFl = 8192)
__global__ void pack_h2(int l) {
    int idx = blockIdx.x * blockDim.x + threadIdx.x;
    if (idx >= HSZ) return;
    int n   = idx >> 12;
    int rem = idx & 4095;
    g_X[n*8192 + rem]        = g_h[l-1][idx];
    g_X[n*8192 + 4096 + rem] = g_h[l][idx];
}

// ---------------- GEMM 1: Y(400 x cols) = SS(400x200) @ X0(200 x cols) ----
// Output rows m=0..399 written to g_X + SEGl (X1 rows 0..199, X2 rows 200..399).
// Dup-broadcast A in shared; f32x2 pairs along cols; double-buffered.
__global__ __launch_bounds__(256) void gemm_support(int BFl, int colBase) {
    __shared__ float As[2][8][132];   // A duplicated: word 2*m_local holds (a,a)
    __shared__ float Bs[2][8][132];
    const int SEGl = 200 * BFl;
    const int m0 = blockIdx.y * 64;
    const int n0 = colBase + blockIdx.x * 128;
    const int t  = threadIdx.x;
    const int ar = t >> 2, ac = (t & 3) * 2;   // A staging: float2 of SS row
    const int br = t >> 5, bc = (t & 31) * 4;  // B staging: float4
    const int tr = t >> 4, tc = t & 15;        // micro: 4 m x 8 cols
    ull acc[4][4] = {};
    const float* Bsrc = g_X + n0 + bc;
    const bool aok = (m0 + ar) < 400;

    float2 av = aok ? *(const float2*)&g_SS[(m0 + ar)*200 + ac] : make_float2(0.f, 0.f);
    float4 bv = *(const float4*)&Bsrc[br*BFl];
    *(ull*)&As[0][ac][2*ar]     = pack2(av.x, av.x);
    *(ull*)&As[0][ac + 1][2*ar] = pack2(av.y, av.y);
    *(float4*)&Bs[0][br][bc] = bv;
    __syncthreads();

    int buf = 0;
    for (int k0 = 0; k0 < 200; k0 += 8) {
        const bool more = (k0 + 8) < 200;
        if (more) {
            av = aok ? *(const float2*)&g_SS[(m0 + ar)*200 + k0 + 8 + ac]
                     : make_float2(0.f, 0.f);
            bv = *(const float4*)&Bsrc[(k0 + 8 + br)*BFl];
        }
        #pragma unroll
        for (int kk = 0; kk < 8; kk++) {
            ulonglong2 a01 = *(const ulonglong2*)&As[buf][kk][tr*8];
            ulonglong2 a23 = *(const ulonglong2*)&As[buf][kk][tr*8 + 4];
            ull am[4] = {a01.x, a01.y, a23.x, a23.y};
            ull bm[4];
            #pragma unroll
            for (int j = 0; j < 4; j++) bm[j] = *(const ull*)&Bs[buf][kk][tc*2 + 32*j];
            #pragma unroll
            for (int i = 0; i < 4; i++)
                #pragma unroll
                for (int j = 0; j < 4; j++) acc[i][j] = ffma2(am[i], bm[j], acc[i][j]);
        }
        if (more) {
            *(ull*)&As[buf^1][ac][2*ar]     = pack2(av.x, av.x);
            *(ull*)&As[buf^1][ac + 1][2*ar] = pack2(av.y, av.y);
            *(float4*)&Bs[buf^1][br][bc] = bv;
        }
        __syncthreads();
        buf ^= 1;
    }
    float* C = g_X + SEGl;
    #pragma unroll
    for (int i = 0; i < 4; i++) {
        int m = m0 + tr*4 + i;
        if (m < 400) {
            #pragma unroll
            for (int j = 0; j < 4; j++)
                *(ull*)&C[m*BFl + n0 + tc*2 + 32*j] = acc[i][j];
        }
    }
}

// ---------------- GEMM 2: combine + epilogue ------------------------------
// One block per node. Rows = 64 batch, cols = O (128 gate / 64 cand), K = 3F.
// f32x2 pairs along batch; weights duplicated in shared at staging.
// MODE 0: sigmoid; r-half -> writes r*h INTO g_X X0 state cols (sole reader =
//         this block, already done reading); u-half -> g_u.
// MODE 1: tanh + GRU update of g_h[layer].
template <int MODE>
__global__ __launch_bounds__(256) void gemm_combine(
    int F, int inDim, int wOff, const float* __restrict__ bias, int layer)
{
    constexpr int O     = (MODE == 0) ? 128 : 64;
    constexpr int PAIRS = (MODE == 0) ? 4 : 2;   // batch pairs per thread
    constexpr int WPT   = O / 32;                // staged weights per thread
    constexpr int OSTR  = O / 4;                 // col stride between thread's o's
    __shared__ float As[2][8][68];
    __shared__ float Ws[2][8][2*O];
    const int BFl = F * 64, SEGl = 200 * BFl;
    const int n = blockIdx.x;
    const int t = threadIdx.x;
    const int sa_k = t >> 5, sa_b = (2*t) & 63;          // A staging: float2
    const int sw_r = t >> 5, sw_o = t & 31;              // W staging
    const int tr = (MODE == 0) ? (t >> 5) : (t >> 4);
    const int tc = (MODE == 0) ? (t & 31) : (t & 15);
    const int bbase = tr * (2 * PAIRS);
    ull acc[PAIRS][4] = {};
    const int NS = 3 * F / 8;

    float2 av; float wv[WPT];
    {   // preload slice 0 (ks=0, f0=0)
        av = *(const float2*)&g_X[n*BFl + sa_k*64 + sa_b];
        #pragma unroll
        for (int q = 0; q < WPT; q++)
            wv[q] = g_W[wOff + sw_r*O + sw_o + 32*q];
        *(float2*)&As[0][sa_k][sa_b] = av;
        #pragma unroll
        for (int q = 0; q < WPT; q++)
            *(ull*)&Ws[0][sw_r][2*(sw_o + 32*q)] = pack2(wv[q], wv[q]);
    }
    __syncthreads();

    int buf = 0;
    for (int s = 0; s < NS; s++) {
        const bool more = (s + 1) < NS;
        if (more) {
            int fs = (s + 1) * 8;
            int ks = (fs >= F) + (fs >= 2*F);
            int f0 = fs - ks * F;
            av = *(const float2*)&g_X[ks*SEGl + n*BFl + (f0 + sa_k)*64 + sa_b];
            const float* Wseg = g_W + wOff + ks*F*O + f0*O;
            #pragma unroll
            for (int q = 0; q < WPT; q++)
                wv[q] = Wseg[sw_r*O + sw_o + 32*q];
        }
        #pragma unroll
        for (int kk = 0; kk < 8; kk++) {
            ull ap[PAIRS];
            {
                ulonglong2 a01 = *(const ulonglong2*)&As[buf][kk][bbase];
                ap[0] = a01.x; ap[1] = a01.y;
                if (MODE == 0) {
                    ulonglong2 a23 = *(const ulonglong2*)&As[buf][kk][bbase + 4];
                    ap[2] = a23.x; ap[3] = a23.y;
                }
            }
            ull wm[4];
            #pragma unroll
            for (int j = 0; j < 4; j++)
                wm[j] = *(const ull*)&Ws[buf][kk][2*(tc + OSTR*j)];
            #pragma unroll
            for (int p = 0; p < PAIRS; p++)
                #pragma unroll
                for (int j = 0; j < 4; j++) acc[p][j] = ffma2(ap[p], wm[j], acc[p][j]);
        }
        if (more) {
            *(float2*)&As[buf^1][sa_k][sa_b] = av;
            #pragma unroll
            for (int q = 0; q < WPT; q++)
                *(ull*)&Ws[buf^1][sw_r][2*(sw_o + 32*q)] = pack2(wv[q], wv[q]);
        }
        __syncthreads();
        buf ^= 1;
    }

    float* hp = g_h[layer];
    #pragma unroll
    for (int p = 0; p < PAIRS; p++) {
        int b = bbase + 2*p;
        #pragma unroll
        for (int j = 0; j < 4; j++) {
            int o = tc + OSTR*j;
            float2 v = upk(acc[p][j]);
            float bo = bias[o];
            v.x += bo; v.y += bo;
            if (MODE == 0) {
                float s0 = 1.f / (1.f + expf(-v.x));
                float s1 = 1.f / (1.f + expf(-v.y));
                if (o < 64) {   // r gate -> r*h into X0 state cols
                    float2 hv = *(const float2*)&hp[n*4096 + o*64 + b];
                    *(ull*)&g_X[n*BFl + (inDim + o)*64 + b] = pack2(s0*hv.x, s1*hv.y);
                } else {        // u gate
                    *(ull*)&g_u[n*4096 + (o - 64)*64 + b] = pack2(s0, s1);
                }
            } else {
                float c0 = tanhf(v.x), c1 = tanhf(v.y);
                float2 uv = *(const float2*)&g_u[n*4096 + o*64 + b];
                float2 hv = *(const float2*)&hp[n*4096 + o*64 + b];
                float h0 = uv.x*hv.x + (1.f - uv.x)*c0;
                float h1 = uv.y*hv.y + (1.f - uv.y)*c1;
                *(ull*)&hp[n*4096 + o*64 + b] = pack2(h0, h1);
            }
        }
    }
}

// ---------------- projection: out_t = h3 @ proj_W + proj_b -------------------
__global__ __launch_bounds__(256) void gemm_proj(const float* __restrict__ W,
                                                 const float* __restrict__ bias,
                                                 float* __restrict__ out, int t) {
    __shared__ float As[8][64];
    __shared__ float Ws[8][64];
    const int n  = blockIdx.y;
    const int o0 = blockIdx.x * 64;
    const int tt = threadIdx.x;
    const int tr = tt >> 4, tc = tt & 15;
    ull acc[4][2];
    #pragma unroll
    for (int i = 0; i < 4; i++) { acc[i][0] = 0ull; acc[i][1] = 0ull; }

    const int ar = tt & 63, ac = tt >> 6;
    const int wr = tt >> 5, wc = (tt & 31) * 2;
    const float* A = g_h[3] + n*4096;

    for (int k0 = 0; k0 < 64; k0 += 8) {
        As[ac][ar]     = A[(k0 + ac)*64 + ar];
        As[ac + 4][ar] = A[(k0 + ac + 4)*64 + ar];
        ull wv = 0ull;
        if (o0 + wc < 200) wv = *(const ull*)&W[(k0 + wr)*200 + o0 + wc];
        *(ull*)&Ws[wr][wc] = wv;
        __syncthreads();
        #pragma unroll
        for (int kk = 0; kk < 8; kk++) {
            ull ap[4];
            #pragma unroll
            for (int i = 0; i < 4; i++) { float a = As[kk][tr*4 + i]; ap[i] = pack2(a, a); }
            ull b0v = *(const ull*)&Ws[kk][tc*2];
            ull b1v = *(const ull*)&Ws[kk][tc*2 + 32];
            #pragma unroll
            for (int i = 0; i < 4; i++) {
                acc[i][0] = ffma2(ap[i], b0v, acc[i][0]);
                acc[i][1] = ffma2(ap[i], b1v, acc[i][1]);
            }
        }
        __syncthreads();
    }
    #pragma unroll
    for (int i = 0; i < 4; i++) {
        int b = tr*4 + i;
        #pragma unroll
        for (int j = 0; j < 2; j++) {
            int o = o0 + tc*2 + 32*j;
            if (o < 200) {
                float2 v = upk(acc[i][j]);
                v.x += bias[o];
                v.y += bias[o + 1];
                *(ull*)&out[b*480000 + t*40000 + n*200 + o] = pack2(v.x, v.y);
            }
        }
    }
}

// ---------------- host driver ----------------
extern "C" void kernel_launch(void* const* d_in, const int* in_sizes, int n_in,
                              void* d_out, int out_size) {
    const float* inputs  = (const float*)d_in[0];
    const float* support = (const float*)d_in[1];
    const float* projW   = (const float*)d_in[18];
    const float* projb   = (const float*)d_in[19];
    float* out = (float*)d_out;

    const float* Wsrc[2][4][2];
    const float* Bsrc[2][4][2];
    for (int s = 0; s < 2; s++) {
        int base = (s == 0) ? 2 : 10;
        Wsrc[s][0][0] = (const float*)d_in[base + 0];
        Bsrc[s][0][0] = (const float*)d_in[base + 1];
        Wsrc[s][0][1] = (const float*)d_in[base + 2];
        Bsrc[s][0][1] = (const float*)d_in[base + 3];
        const float* Wg = (const float*)d_in[base + 4];
        const float* Bg = (const float*)d_in[base + 5];
        const float* Wc = (const float*)d_in[base + 6];
        const float* Bc = (const float*)d_in[base + 7];
        for (int l = 1; l < 4; l++) {
            Wsrc[s][l][0] = Wg + (l - 1) * 384 * 128;
            Bsrc[s][l][0] = Bg + (l - 1) * 128;
            Wsrc[s][l][1] = Wc + (l - 1) * 384 * 64;
            Bsrc[s][l][1] = Bc + (l - 1) * 64;
        }
    }
    int wOff[2][4][2];
    for (int s = 0; s < 2; s++) {
        int base = s * 373248;
        wOff[s][0][0] = base;
        wOff[s][0][1] = base + 101376;
        for (int l = 1; l < 4; l++) {
            wOff[s][l][0] = base + 152064 + (l - 1) * 73728;
            wOff[s][l][1] = wOff[s][l][0] + 49152;
        }
    }

    // setup (deterministic, cheap)
    build_SS<<<400, 256>>>(support);
    zero_h<<<(NL*HSZ + 255) / 256, 256>>>();
    for (int s = 0; s < 2; s++)
        for (int l = 0; l < 4; l++) {
            int F = (l == 0) ? F0 : F1;
            reorder_W<<<(3*F*128 + 255) / 256, 256>>>(Wsrc[s][l][0], wOff[s][l][0], F, 128);
            reorder_W<<<(3*F*64  + 255) / 256, 256>>>(Wsrc[s][l][1], wOff[s][l][1], F, 64);
        }

    auto cell = [&](int s, int l, const float* l0src) {
        int F     = (l == 0) ? F0 : F1;
        int BFl   = F * 64;
        int inDim = F - 64;

        if (l == 0) {
            pack_l0_input<<<dim3(200, 7, 2), dim3(32, 8)>>>(l0src, 480000);
            pack_h_block<<<(HSZ + 255) / 256, 256>>>(0, 200, BF0);
        } else {
            pack_h2<<<(HSZ + 255) / 256, 256>>>(l);
        }
        // gate pass: diffuse all cols of [x, h]; gates (r*h fused into X0, u)
        gemm_support<<<dim3(BFl / 128, 7), 256>>>(BFl, 0);
        gemm_combine<0><<<200, 256>>>(F, inDim, wOff[s][l][0], Bsrc[s][l][0], l);
        // candidate pass: re-diffuse only the state cols (now r*h)
        gemm_support<<<dim3(32, 7), 256>>>(BFl, inDim * 64);
        gemm_combine<1><<<200, 256>>>(F, inDim, wOff[s][l][1], Bsrc[s][l][1], l);
    };

    // encoder
    for (int t = 0; t < NT; t++) {
        cell(0, 0, inputs + t * NNSQ);
        for (int l = 1; l < 4; l++) cell(0, l, nullptr);
    }
    // decoder
    for (int t = 0; t < NT; t++) {
        cell(1, 0, (t == 0) ? nullptr : out + (t - 1) * NNSQ);
        for (int l = 1; l < 4; l++) cell(1, l, nullptr);
        gemm_proj<<<dim3(4, 200), 256>>>(projW, projb, out, t);
    }
    (void)in_sizes; (void)n_in; (void)out_size;
}